// round 14
// baseline (speedup 1.0000x reference)
#include <cuda_runtime.h>
#include <cstdint>
#include <math.h>

#define SEQ 20
#define H   128
#define NC  100000

// Scratch (allocation-free rule: __device__ globals)
__device__ float g_comb[SEQ * 256];   // [t][ fwd(128) | bwd(128) ]
__device__ float g_fb[SEQ * 256];     // [t][256]  output of 2H LSTM

// ---------------------------------------------------------------------------
// Fast transcendentals via MUFU (ex2/rcp approx are ~2^-22 accurate).
// sigm(x) = 1/(1+2^(-x*log2e)) ; tanh(x) = 2*sigm(2x)-1
// ---------------------------------------------------------------------------
__device__ __forceinline__ float ex2f(float x) { float y; asm("ex2.approx.f32 %0, %1;" : "=f"(y) : "f"(x)); return y; }
__device__ __forceinline__ float rcpf(float x) { float y; asm("rcp.approx.f32 %0, %1;" : "=f"(y) : "f"(x)); return y; }
__device__ __forceinline__ float sigm(float x) {
    return rcpf(1.0f + ex2f(-1.4426950408889634f * x));
}
__device__ __forceinline__ float tanh_fast(float x) {
    return fmaf(2.0f, rcpf(1.0f + ex2f(-2.8853900817779268f * x)), -1.0f);
}

// ---------------------------------------------------------------------------
// DSMEM / mbarrier helpers
// ---------------------------------------------------------------------------
__device__ __forceinline__ uint32_t smem_u32(const void* p) {
    return (uint32_t)__cvta_generic_to_shared(p);
}
__device__ __forceinline__ uint32_t mapa_rank(uint32_t laddr, uint32_t rank) {
    uint32_t r;
    asm("mapa.shared::cluster.u32 %0, %1, %2;" : "=r"(r) : "r"(laddr), "r"(rank));
    return r;
}
__device__ __forceinline__ void st_remote_f32(uint32_t raddr, float v) {
    asm volatile("st.shared::cluster.f32 [%0], %1;" :: "r"(raddr), "f"(v) : "memory");
}
__device__ __forceinline__ void mbar_init(uint32_t laddr, uint32_t cnt) {
    asm volatile("mbarrier.init.shared.b64 [%0], %1;" :: "r"(laddr), "r"(cnt) : "memory");
}
__device__ __forceinline__ void mbar_arrive_remote_rel(uint32_t raddr) {
    asm volatile("mbarrier.arrive.release.cluster.shared::cluster.b64 _, [%0];"
                 :: "r"(raddr) : "memory");
}
__device__ __forceinline__ void mbar_wait_cluster(uint32_t laddr, uint32_t parity) {
    asm volatile(
        "{\n\t"
        ".reg .pred P;\n\t"
        "WL%=:\n\t"
        "mbarrier.try_wait.parity.acquire.cluster.shared::cta.b64 P, [%0], %1, 0x989680;\n\t"
        "@P bra WD%=;\n\t"
        "bra WL%=;\n\t"
        "WD%=:\n\t"
        "}"
        :: "r"(laddr), "r"(parity) : "memory");
}
#define CLUSTER_SYNC() do { \
    asm volatile("barrier.cluster.arrive.aligned;" ::: "memory"); \
    asm volatile("barrier.cluster.wait.aligned;"   ::: "memory"); } while (0)

// ============================================================================
// Kernel 1: forward + backward H=128 LSTM scans.
// grid = 8, cluster = 4: cluster 0 (blocks 0-3) = forward cell,
// cluster 1 (blocks 4-7) = backward cell. Each CTA owns 32 units
// (128 gate rows); each gate row's [Wih|Whh] (256 w) is split over
// 4 threads (64 weights in registers each). Per-step h broadcast via
// DSMEM stores + mbarrier (no cluster barrier in the loop).
// ============================================================================
__global__ void __launch_bounds__(512, 1) __cluster_dims__(4, 1, 1)
lstm_fb_kernel(const float* __restrict__ x,
               const float* __restrict__ h0f, const float* __restrict__ c0f,
               const float* __restrict__ h0b, const float* __restrict__ c0b,
               const float* __restrict__ Wih_f, const float* __restrict__ Whh_f,
               const float* __restrict__ bih_f, const float* __restrict__ bhh_f,
               const float* __restrict__ Wih_b, const float* __restrict__ Whh_b,
               const float* __restrict__ bih_b, const float* __restrict__ bhh_b)
{
    __shared__ float xs[SEQ * H];      // 10 KB
    __shared__ float hbuf[2][H];       // double-buffered hidden
    __shared__ float gates[128];
    __shared__ __align__(8) uint64_t mbar[2];

    const int tid  = threadIdx.x;
    const int cell = blockIdx.x >> 2;  // 0 = fwd, 1 = bwd
    uint32_t rank;                     // rank within 4-CTA cluster
    asm("mov.u32 %0, %%cluster_ctarank;" : "=r"(rank));
    const int cblk = (int)rank;

    const float* Wih = cell ? Wih_b : Wih_f;
    const float* Whh = cell ? Whh_b : Whh_f;
    const float* bih = cell ? bih_b : bih_f;
    const float* bhh = cell ? bhh_b : bhh_f;
    const float* h0  = cell ? h0b : h0f;
    const float* c0  = cell ? c0b : c0f;

    const int gl   = tid >> 2;         // 0..127 local gate
    const int seg  = tid & 3;          // 64-weight segment
    const int type = gl >> 5;          // i,f,g,o
    const int ul   = gl & 31;
    const int u    = cblk * 32 + ul;   // unit within cell (0..127)
    const int g    = type * H + u;     // gate row in [0,512)

    // Register-resident weights: seg 0/1 -> Wih halves, seg 2/3 -> Whh halves.
    float w[64];
    {
        const float* wsrc = (seg < 2) ? (Wih + (size_t)g * H + seg * 64)
                                      : (Whh + (size_t)g * H + (seg - 2) * 64);
        #pragma unroll
        for (int q = 0; q < 16; q++) {
            float4 v = *(const float4*)(wsrc + q * 4);
            w[q*4+0] = v.x; w[q*4+1] = v.y; w[q*4+2] = v.z; w[q*4+3] = v.w;
        }
    }
    const float bias = bih[g] + bhh[g];

    if (tid == 0) {
        mbar_init(smem_u32(&mbar[0]), 4);
        mbar_init(smem_u32(&mbar[1]), 4);
        asm volatile("fence.mbarrier_init.release.cluster;" ::: "memory");
    }
    for (int i = tid; i < SEQ * H; i += 512) xs[i] = x[i];
    if (tid < H) hbuf[0][tid] = h0[tid];
    float creg = 0.0f;
    if (tid < 32) creg = c0[cblk * 32 + tid];
    __syncthreads();
    CLUSTER_SYNC();   // publish mbarrier inits cluster-wide

    #pragma unroll 1
    for (int t = 0; t < SEQ; t++) {
        const int cur = t & 1, nxt = cur ^ 1;
        if (t > 0) mbar_wait_cluster(smem_u32(&mbar[cur]), ((t - 1) >> 1) & 1);

        const int tx = cell ? (SEQ - 1 - t) : t;   // backward scans reversed x
        const float* vsrc = (seg < 2) ? (xs + tx * H + seg * 64)
                                      : (hbuf[cur] + (seg - 2) * 64);
        float a0 = 0.f, a1 = 0.f, a2 = 0.f, a3 = 0.f;
        #pragma unroll
        for (int q = 0; q < 16; q++) {
            float4 v = *(const float4*)(vsrc + q * 4);
            a0 += w[q*4+0] * v.x; a1 += w[q*4+1] * v.y;
            a2 += w[q*4+2] * v.z; a3 += w[q*4+3] * v.w;
        }
        float s = (a0 + a1) + (a2 + a3);
        s += __shfl_xor_sync(0xffffffffu, s, 1);
        s += __shfl_xor_sync(0xffffffffu, s, 2);
        if (seg == 0) gates[gl] = s + bias;
        __syncthreads();

        if (tid < 32) {
            const float gi = gates[tid],      gf = gates[32 + tid];
            const float gc = gates[64 + tid], go = gates[96 + tid];
            creg = sigm(gf) * creg + sigm(gi) * tanh_fast(gc);
            const float h2 = sigm(go) * tanh_fast(creg);
            g_comb[t * 256 + cell * 128 + cblk * 32 + tid] = h2;
            if (t < SEQ - 1) {
                const uint32_t laddr = smem_u32(&hbuf[nxt][cblk * 32 + tid]);
                #pragma unroll
                for (int r = 0; r < 4; r++) st_remote_f32(mapa_rank(laddr, r), h2);
                __syncwarp();
                if (tid == 0) {
                    const uint32_t mb = smem_u32(&mbar[nxt]);
                    #pragma unroll
                    for (int r = 0; r < 4; r++) mbar_arrive_remote_rel(mapa_rank(mb, r));
                }
            }
        }
    }
}

// ============================================================================
// Kernel 2: 2H=256 LSTM over comb. 8-CTA cluster; each CTA owns 32 of 256
// units (128 gate rows of 8H=1024). Phase A precomputes the x contribution
// xg[t][g] = Wih_l[g]·comb[t] + biases for ALL t in parallel. The serial
// scan then only needs Whh_l (register-resident) + mbarrier h broadcast.
// ============================================================================
__global__ void __launch_bounds__(512, 1) __cluster_dims__(8, 1, 1)
lstm_l_kernel(const float* __restrict__ h0l, const float* __restrict__ c0l,
              const float* __restrict__ Wih_l, const float* __restrict__ Whh_l,
              const float* __restrict__ bih_l, const float* __restrict__ bhh_l)
{
    __shared__ float combs[SEQ * 256];   // 20 KB
    __shared__ float xg[SEQ * 128];      // 10 KB  (per-CTA gate slice)
    __shared__ float hbuf[2][256];
    __shared__ float gates[128];
    __shared__ __align__(8) uint64_t mbar[2];

    const int tid  = threadIdx.x;
    uint32_t rank;
    asm("mov.u32 %0, %%cluster_ctarank;" : "=r"(rank));
    const int gl   = tid >> 2;
    const int seg  = tid & 3;
    const int type = gl >> 5;
    const int ul   = gl & 31;
    const int u    = (int)rank * 32 + ul;  // unit in [0,256)
    const int g    = type * 256 + u;       // gate row in [0,1024)

    if (tid == 0) {
        mbar_init(smem_u32(&mbar[0]), 8);
        mbar_init(smem_u32(&mbar[1]), 8);
        asm volatile("fence.mbarrier_init.release.cluster;" ::: "memory");
    }
    for (int i = tid; i < SEQ * 256; i += 512) combs[i] = g_comb[i];
    if (tid < 256) hbuf[0][tid] = h0l[tid];
    float creg = 0.0f;
    if (tid < 32) creg = c0l[(int)rank * 32 + tid];
    const float bias = bih_l[g] + bhh_l[g];
    __syncthreads();

    float w[64];
    // ---- Phase A: xg for all timesteps (Wih_l temporarily in w[]) ----
    {
        const float* wsrc = Wih_l + (size_t)g * 256 + seg * 64;
        #pragma unroll
        for (int q = 0; q < 16; q++) {
            float4 v = *(const float4*)(wsrc + q * 4);
            w[q*4+0] = v.x; w[q*4+1] = v.y; w[q*4+2] = v.z; w[q*4+3] = v.w;
        }
        #pragma unroll 1
        for (int t = 0; t < SEQ; t++) {
            const float* vs = combs + t * 256 + seg * 64;
            float a0 = 0.f, a1 = 0.f, a2 = 0.f, a3 = 0.f;
            #pragma unroll
            for (int q = 0; q < 16; q++) {
                float4 v = *(const float4*)(vs + q * 4);
                a0 += w[q*4+0] * v.x; a1 += w[q*4+1] * v.y;
                a2 += w[q*4+2] * v.z; a3 += w[q*4+3] * v.w;
            }
            float s = (a0 + a1) + (a2 + a3);
            s += __shfl_xor_sync(0xffffffffu, s, 1);
            s += __shfl_xor_sync(0xffffffffu, s, 2);
            if (seg == 0) xg[t * 128 + gl] = s + bias;
        }
    }
    // ---- reload w[] with Whh_l row segment ----
    {
        const float* wsrc = Whh_l + (size_t)g * 256 + seg * 64;
        #pragma unroll
        for (int q = 0; q < 16; q++) {
            float4 v = *(const float4*)(wsrc + q * 4);
            w[q*4+0] = v.x; w[q*4+1] = v.y; w[q*4+2] = v.z; w[q*4+3] = v.w;
        }
    }
    __syncthreads();
    CLUSTER_SYNC();   // publish mbarrier inits cluster-wide

    #pragma unroll 1
    for (int t = 0; t < SEQ; t++) {
        const int cur = t & 1, nxt = cur ^ 1;
        if (t > 0) mbar_wait_cluster(smem_u32(&mbar[cur]), ((t - 1) >> 1) & 1);

        const float* vs = hbuf[cur] + seg * 64;
        float a0 = 0.f, a1 = 0.f, a2 = 0.f, a3 = 0.f;
        #pragma unroll
        for (int q = 0; q < 16; q++) {
            float4 v = *(const float4*)(vs + q * 4);
            a0 += w[q*4+0] * v.x; a1 += w[q*4+1] * v.y;
            a2 += w[q*4+2] * v.z; a3 += w[q*4+3] * v.w;
        }
        float s = (a0 + a1) + (a2 + a3);
        s += __shfl_xor_sync(0xffffffffu, s, 1);
        s += __shfl_xor_sync(0xffffffffu, s, 2);
        if (seg == 0) gates[gl] = s + xg[t * 128 + gl];
        __syncthreads();

        if (tid < 32) {
            const float gi = gates[tid],      gf = gates[32 + tid];
            const float gc = gates[64 + tid], go = gates[96 + tid];
            creg = sigm(gf) * creg + sigm(gi) * tanh_fast(gc);
            const float h2 = sigm(go) * tanh_fast(creg);
            g_fb[t * 256 + (int)rank * 32 + tid] = h2;
            if (t < SEQ - 1) {
                const uint32_t laddr = smem_u32(&hbuf[nxt][(int)rank * 32 + tid]);
                #pragma unroll
                for (int r = 0; r < 8; r++) st_remote_f32(mapa_rank(laddr, r), h2);
                __syncwarp();
                if (tid == 0) {
                    const uint32_t mb = smem_u32(&mbar[nxt]);
                    #pragma unroll
                    for (int r = 0; r < 8; r++) mbar_arrive_remote_rel(mapa_rank(mb, r));
                }
            }
        }
    }
}

// ============================================================================
// Kernel 3: out[t][n] = fb[t]·Wlin[n] + blin[n]   (20 x 100000, K=256)
// HBM-bound on Wlin (102.4 MB). smem-tiled, packed f32x2 FMA: each thread
// owns one column n with 10 packed accumulators (20 timesteps).
// Ws padded to stride 20 (16B aligned, conflict-free LDS.128 weight loads).
// ============================================================================
__global__ void __launch_bounds__(256, 4)
proj_kernel(const float* __restrict__ Wlin, const float* __restrict__ blin,
            float* __restrict__ out)
{
    __shared__ float fbT[256 * 20];   // [k][t], row stride 20 floats (16B-aligned)
    __shared__ float Ws[256 * 20];    // [n_local][16 k + 4 pad], 16B-aligned rows

    const int tid = threadIdx.x;
    const int n0  = blockIdx.x * 256;
    const int n   = n0 + tid;
    const bool valid = (n < NC);

    // fbT: transpose fb[20][256] -> fbT[k][t]; tid == k
    #pragma unroll
    for (int t = 0; t < SEQ; t++) fbT[tid * 20 + t] = g_fb[t * 256 + tid];

    const float bb = valid ? blin[n] : 0.0f;
    unsigned long long acc[10];
    {
        const uint32_t bu = __float_as_uint(bb);
        #pragma unroll
        for (int j = 0; j < 10; j++)
            asm("mov.b64 %0, {%1, %1};" : "=l"(acc[j]) : "r"(bu));
    }
    __syncthreads();

    #pragma unroll 1
    for (int kt = 0; kt < 16; kt++) {
        // Stage Wlin tile: 256 rows x 16 cols, coalesced float4 loads.
        #pragma unroll
        for (int it = 0; it < 4; it++) {
            const int idx = tid + it * 256;           // 0..1023
            const int row = idx >> 2, cs = idx & 3;
            float4 v = make_float4(0.f, 0.f, 0.f, 0.f);
            const int nr = n0 + row;
            if (nr < NC)
                v = *(const float4*)(Wlin + (size_t)nr * 256 + kt * 16 + cs * 4);
            *(float4*)&Ws[row * 20 + cs * 4] = v;
        }
        __syncthreads();

        #pragma unroll
        for (int kk4 = 0; kk4 < 4; kk4++) {
            const float4 wv = *(const float4*)&Ws[tid * 20 + kk4 * 4];
            const float wf[4] = {wv.x, wv.y, wv.z, wv.w};
            #pragma unroll
            for (int j = 0; j < 4; j++) {
                unsigned long long w2;
                asm("mov.b64 %0, {%1, %1};" : "=l"(w2) : "r"(__float_as_uint(wf[j])));
                const ulonglong2* fp =
                    (const ulonglong2*)&fbT[(kt * 16 + kk4 * 4 + j) * 20];
                #pragma unroll
                for (int q = 0; q < 5; q++) {
                    const ulonglong2 fv = fp[q];   // broadcast LDS.128
                    asm("fma.rn.f32x2 %0, %1, %2, %0;" : "+l"(acc[2*q])   : "l"(w2), "l"(fv.x));
                    asm("fma.rn.f32x2 %0, %1, %2, %0;" : "+l"(acc[2*q+1]) : "l"(w2), "l"(fv.y));
                }
            }
        }
        __syncthreads();
    }

    if (valid) {
        #pragma unroll
        for (int j = 0; j < 10; j++) {
            uint32_t lo, hi;
            asm("mov.b64 {%0, %1}, %2;" : "=r"(lo), "=r"(hi) : "l"(acc[j]));
            out[(size_t)(2 * j)     * NC + n] = __uint_as_float(lo);
            out[(size_t)(2 * j + 1) * NC + n] = __uint_as_float(hi);
        }
    }
}

// ============================================================================
// Launch
// ============================================================================
extern "C" void kernel_launch(void* const* d_in, const int* in_sizes, int n_in,
                              void* d_out, int out_size)
{
    (void)in_sizes; (void)n_in; (void)out_size;
    const float* x     = (const float*)d_in[0];
    const float* h0f   = (const float*)d_in[1];
    const float* c0f   = (const float*)d_in[2];
    const float* h0b   = (const float*)d_in[3];
    const float* c0b   = (const float*)d_in[4];
    const float* h0l   = (const float*)d_in[5];
    const float* c0l   = (const float*)d_in[6];
    const float* Wih_f = (const float*)d_in[7];
    const float* Whh_f = (const float*)d_in[8];
    const float* bih_f = (const float*)d_in[9];
    const float* bhh_f = (const float*)d_in[10];
    const float* Wih_b = (const float*)d_in[11];
    const float* Whh_b = (const float*)d_in[12];
    const float* bih_b = (const float*)d_in[13];
    const float* bhh_b = (const float*)d_in[14];
    const float* Wih_l = (const float*)d_in[15];
    const float* Whh_l = (const float*)d_in[16];
    const float* bih_l = (const float*)d_in[17];
    const float* bhh_l = (const float*)d_in[18];
    const float* Wlin  = (const float*)d_in[19];
    const float* blin  = (const float*)d_in[20];
    float* out = (float*)d_out;

    lstm_fb_kernel<<<8, 512>>>(x, h0f, c0f, h0b, c0b,
                               Wih_f, Whh_f, bih_f, bhh_f,
                               Wih_b, Whh_b, bih_b, bhh_b);
    lstm_l_kernel<<<8, 512>>>(h0l, c0l, Wih_l, Whh_l, bih_l, bhh_l);
    proj_kernel<<<(NC + 255) / 256, 256>>>(Wlin, blin, out);
}

// round 15
// speedup vs baseline: 1.0094x; 1.0094x over previous
#include <cuda_runtime.h>
#include <cstdint>
#include <math.h>

#define SEQ 20
#define H   128
#define NC  100000

// Scratch (allocation-free rule: __device__ globals)
__device__ float g_comb[SEQ * 256];   // [t][ fwd(128) | bwd(128) ]
__device__ float g_fb[SEQ * 256];     // [t][256]  output of 2H LSTM

// ---------------------------------------------------------------------------
// Fast transcendentals via MUFU (ex2/rcp approx are ~2^-22 accurate).
// sigm(x) = 1/(1+2^(-x*log2e)) ; tanh(x) = 2*sigm(2x)-1
// ---------------------------------------------------------------------------
__device__ __forceinline__ float ex2f(float x) { float y; asm("ex2.approx.f32 %0, %1;" : "=f"(y) : "f"(x)); return y; }
__device__ __forceinline__ float rcpf(float x) { float y; asm("rcp.approx.f32 %0, %1;" : "=f"(y) : "f"(x)); return y; }
__device__ __forceinline__ float sigm(float x) {
    return rcpf(1.0f + ex2f(-1.4426950408889634f * x));
}
__device__ __forceinline__ float tanh_fast(float x) {
    return fmaf(2.0f, rcpf(1.0f + ex2f(-2.8853900817779268f * x)), -1.0f);
}

// ---------------------------------------------------------------------------
// DSMEM / mbarrier helpers
// ---------------------------------------------------------------------------
__device__ __forceinline__ uint32_t smem_u32(const void* p) {
    return (uint32_t)__cvta_generic_to_shared(p);
}
__device__ __forceinline__ uint32_t mapa_rank(uint32_t laddr, uint32_t rank) {
    uint32_t r;
    asm("mapa.shared::cluster.u32 %0, %1, %2;" : "=r"(r) : "r"(laddr), "r"(rank));
    return r;
}
__device__ __forceinline__ void st_remote_f32(uint32_t raddr, float v) {
    asm volatile("st.shared::cluster.f32 [%0], %1;" :: "r"(raddr), "f"(v) : "memory");
}
__device__ __forceinline__ void mbar_init(uint32_t laddr, uint32_t cnt) {
    asm volatile("mbarrier.init.shared.b64 [%0], %1;" :: "r"(laddr), "r"(cnt) : "memory");
}
__device__ __forceinline__ void mbar_arrive_remote_rel(uint32_t raddr) {
    asm volatile("mbarrier.arrive.release.cluster.shared::cluster.b64 _, [%0];"
                 :: "r"(raddr) : "memory");
}
__device__ __forceinline__ void mbar_wait_cluster(uint32_t laddr, uint32_t parity) {
    asm volatile(
        "{\n\t"
        ".reg .pred P;\n\t"
        "WL%=:\n\t"
        "mbarrier.try_wait.parity.acquire.cluster.shared::cta.b64 P, [%0], %1, 0x989680;\n\t"
        "@P bra WD%=;\n\t"
        "bra WL%=;\n\t"
        "WD%=:\n\t"
        "}"
        :: "r"(laddr), "r"(parity) : "memory");
}
#define CLUSTER_SYNC() do { \
    asm volatile("barrier.cluster.arrive.aligned;" ::: "memory"); \
    asm volatile("barrier.cluster.wait.aligned;"   ::: "memory"); } while (0)

// ============================================================================
// Kernel 1: forward + backward H=128 LSTM scans.
// grid = 8, cluster = 4: cluster 0 (blocks 0-3) = forward cell,
// cluster 1 (blocks 4-7) = backward cell. Each CTA owns 32 units
// (128 gate rows); each gate row's [Wih|Whh] (256 w) is split over
// 4 threads (64 weights in registers each). Per-step h broadcast via
// DSMEM stores + mbarrier (no cluster barrier in the loop).
// ============================================================================
__global__ void __launch_bounds__(512, 1) __cluster_dims__(4, 1, 1)
lstm_fb_kernel(const float* __restrict__ x,
               const float* __restrict__ h0f, const float* __restrict__ c0f,
               const float* __restrict__ h0b, const float* __restrict__ c0b,
               const float* __restrict__ Wih_f, const float* __restrict__ Whh_f,
               const float* __restrict__ bih_f, const float* __restrict__ bhh_f,
               const float* __restrict__ Wih_b, const float* __restrict__ Whh_b,
               const float* __restrict__ bih_b, const float* __restrict__ bhh_b)
{
    __shared__ float xs[SEQ * H];      // 10 KB
    __shared__ float hbuf[2][H];       // double-buffered hidden
    __shared__ float gates[128];
    __shared__ __align__(8) uint64_t mbar[2];

    const int tid  = threadIdx.x;
    const int cell = blockIdx.x >> 2;  // 0 = fwd, 1 = bwd
    uint32_t rank;                     // rank within 4-CTA cluster
    asm("mov.u32 %0, %%cluster_ctarank;" : "=r"(rank));
    const int cblk = (int)rank;

    const float* Wih = cell ? Wih_b : Wih_f;
    const float* Whh = cell ? Whh_b : Whh_f;
    const float* bih = cell ? bih_b : bih_f;
    const float* bhh = cell ? bhh_b : bhh_f;
    const float* h0  = cell ? h0b : h0f;
    const float* c0  = cell ? c0b : c0f;

    const int gl   = tid >> 2;         // 0..127 local gate
    const int seg  = tid & 3;          // 64-weight segment
    const int type = gl >> 5;          // i,f,g,o
    const int ul   = gl & 31;
    const int u    = cblk * 32 + ul;   // unit within cell (0..127)
    const int g    = type * H + u;     // gate row in [0,512)

    // Register-resident weights: seg 0/1 -> Wih halves, seg 2/3 -> Whh halves.
    float w[64];
    {
        const float* wsrc = (seg < 2) ? (Wih + (size_t)g * H + seg * 64)
                                      : (Whh + (size_t)g * H + (seg - 2) * 64);
        #pragma unroll
        for (int q = 0; q < 16; q++) {
            float4 v = *(const float4*)(wsrc + q * 4);
            w[q*4+0] = v.x; w[q*4+1] = v.y; w[q*4+2] = v.z; w[q*4+3] = v.w;
        }
    }
    const float bias = bih[g] + bhh[g];

    if (tid == 0) {
        mbar_init(smem_u32(&mbar[0]), 4);
        mbar_init(smem_u32(&mbar[1]), 4);
        asm volatile("fence.mbarrier_init.release.cluster;" ::: "memory");
    }
    for (int i = tid; i < SEQ * H; i += 512) xs[i] = x[i];
    if (tid < H) hbuf[0][tid] = h0[tid];
    float creg = 0.0f;
    if (tid < 32) creg = c0[cblk * 32 + tid];
    __syncthreads();
    CLUSTER_SYNC();   // publish mbarrier inits cluster-wide

    #pragma unroll 1
    for (int t = 0; t < SEQ; t++) {
        const int cur = t & 1, nxt = cur ^ 1;
        if (t > 0) mbar_wait_cluster(smem_u32(&mbar[cur]), ((t - 1) >> 1) & 1);

        const int tx = cell ? (SEQ - 1 - t) : t;   // backward scans reversed x
        const float* vsrc = (seg < 2) ? (xs + tx * H + seg * 64)
                                      : (hbuf[cur] + (seg - 2) * 64);
        float a0 = 0.f, a1 = 0.f, a2 = 0.f, a3 = 0.f;
        #pragma unroll
        for (int q = 0; q < 16; q++) {
            float4 v = *(const float4*)(vsrc + q * 4);
            a0 += w[q*4+0] * v.x; a1 += w[q*4+1] * v.y;
            a2 += w[q*4+2] * v.z; a3 += w[q*4+3] * v.w;
        }
        float s = (a0 + a1) + (a2 + a3);
        s += __shfl_xor_sync(0xffffffffu, s, 1);
        s += __shfl_xor_sync(0xffffffffu, s, 2);
        if (seg == 0) gates[gl] = s + bias;
        __syncthreads();

        if (tid < 32) {
            const float gi = gates[tid],      gf = gates[32 + tid];
            const float gc = gates[64 + tid], go = gates[96 + tid];
            creg = sigm(gf) * creg + sigm(gi) * tanh_fast(gc);
            const float h2 = sigm(go) * tanh_fast(creg);
            g_comb[t * 256 + cell * 128 + cblk * 32 + tid] = h2;
            if (t < SEQ - 1) {
                const uint32_t laddr = smem_u32(&hbuf[nxt][cblk * 32 + tid]);
                #pragma unroll
                for (int r = 0; r < 4; r++) st_remote_f32(mapa_rank(laddr, r), h2);
                __syncwarp();
                if (tid == 0) {
                    const uint32_t mb = smem_u32(&mbar[nxt]);
                    #pragma unroll
                    for (int r = 0; r < 4; r++) mbar_arrive_remote_rel(mapa_rank(mb, r));
                }
            }
        }
    }
}

// ============================================================================
// Kernel 2: 2H=256 LSTM over comb. 8-CTA cluster; each CTA owns 32 of 256
// units (128 gate rows of 8H=1024). Phase A precomputes the x contribution
// xg[t][g] = Wih_l[g]·comb[t] + biases for ALL t in parallel. The serial
// scan then only needs Whh_l (register-resident) + mbarrier h broadcast.
// ============================================================================
__global__ void __launch_bounds__(512, 1) __cluster_dims__(8, 1, 1)
lstm_l_kernel(const float* __restrict__ h0l, const float* __restrict__ c0l,
              const float* __restrict__ Wih_l, const float* __restrict__ Whh_l,
              const float* __restrict__ bih_l, const float* __restrict__ bhh_l)
{
    __shared__ float combs[SEQ * 256];   // 20 KB
    __shared__ float xg[SEQ * 128];      // 10 KB  (per-CTA gate slice)
    __shared__ float hbuf[2][256];
    __shared__ float gates[128];
    __shared__ __align__(8) uint64_t mbar[2];

    const int tid  = threadIdx.x;
    uint32_t rank;
    asm("mov.u32 %0, %%cluster_ctarank;" : "=r"(rank));
    const int gl   = tid >> 2;
    const int seg  = tid & 3;
    const int type = gl >> 5;
    const int ul   = gl & 31;
    const int u    = (int)rank * 32 + ul;  // unit in [0,256)
    const int g    = type * 256 + u;       // gate row in [0,1024)

    if (tid == 0) {
        mbar_init(smem_u32(&mbar[0]), 8);
        mbar_init(smem_u32(&mbar[1]), 8);
        asm volatile("fence.mbarrier_init.release.cluster;" ::: "memory");
    }
    for (int i = tid; i < SEQ * 256; i += 512) combs[i] = g_comb[i];
    if (tid < 256) hbuf[0][tid] = h0l[tid];
    float creg = 0.0f;
    if (tid < 32) creg = c0l[(int)rank * 32 + tid];
    const float bias = bih_l[g] + bhh_l[g];
    __syncthreads();

    float w[64];
    // ---- Phase A: xg for all timesteps (Wih_l temporarily in w[]) ----
    {
        const float* wsrc = Wih_l + (size_t)g * 256 + seg * 64;
        #pragma unroll
        for (int q = 0; q < 16; q++) {
            float4 v = *(const float4*)(wsrc + q * 4);
            w[q*4+0] = v.x; w[q*4+1] = v.y; w[q*4+2] = v.z; w[q*4+3] = v.w;
        }
        #pragma unroll 1
        for (int t = 0; t < SEQ; t++) {
            const float* vs = combs + t * 256 + seg * 64;
            float a0 = 0.f, a1 = 0.f, a2 = 0.f, a3 = 0.f;
            #pragma unroll
            for (int q = 0; q < 16; q++) {
                float4 v = *(const float4*)(vs + q * 4);
                a0 += w[q*4+0] * v.x; a1 += w[q*4+1] * v.y;
                a2 += w[q*4+2] * v.z; a3 += w[q*4+3] * v.w;
            }
            float s = (a0 + a1) + (a2 + a3);
            s += __shfl_xor_sync(0xffffffffu, s, 1);
            s += __shfl_xor_sync(0xffffffffu, s, 2);
            if (seg == 0) xg[t * 128 + gl] = s + bias;
        }
    }
    // ---- reload w[] with Whh_l row segment ----
    {
        const float* wsrc = Whh_l + (size_t)g * 256 + seg * 64;
        #pragma unroll
        for (int q = 0; q < 16; q++) {
            float4 v = *(const float4*)(wsrc + q * 4);
            w[q*4+0] = v.x; w[q*4+1] = v.y; w[q*4+2] = v.z; w[q*4+3] = v.w;
        }
    }
    __syncthreads();
    CLUSTER_SYNC();   // publish mbarrier inits cluster-wide

    #pragma unroll 1
    for (int t = 0; t < SEQ; t++) {
        const int cur = t & 1, nxt = cur ^ 1;
        if (t > 0) mbar_wait_cluster(smem_u32(&mbar[cur]), ((t - 1) >> 1) & 1);

        const float* vs = hbuf[cur] + seg * 64;
        float a0 = 0.f, a1 = 0.f, a2 = 0.f, a3 = 0.f;
        #pragma unroll
        for (int q = 0; q < 16; q++) {
            float4 v = *(const float4*)(vs + q * 4);
            a0 += w[q*4+0] * v.x; a1 += w[q*4+1] * v.y;
            a2 += w[q*4+2] * v.z; a3 += w[q*4+3] * v.w;
        }
        float s = (a0 + a1) + (a2 + a3);
        s += __shfl_xor_sync(0xffffffffu, s, 1);
        s += __shfl_xor_sync(0xffffffffu, s, 2);
        if (seg == 0) gates[gl] = s + xg[t * 128 + gl];
        __syncthreads();

        if (tid < 32) {
            const float gi = gates[tid],      gf = gates[32 + tid];
            const float gc = gates[64 + tid], go = gates[96 + tid];
            creg = sigm(gf) * creg + sigm(gi) * tanh_fast(gc);
            const float h2 = sigm(go) * tanh_fast(creg);
            g_fb[t * 256 + (int)rank * 32 + tid] = h2;
            if (t < SEQ - 1) {
                const uint32_t laddr = smem_u32(&hbuf[nxt][(int)rank * 32 + tid]);
                #pragma unroll
                for (int r = 0; r < 8; r++) st_remote_f32(mapa_rank(laddr, r), h2);
                __syncwarp();
                if (tid == 0) {
                    const uint32_t mb = smem_u32(&mbar[nxt]);
                    #pragma unroll
                    for (int r = 0; r < 8; r++) mbar_arrive_remote_rel(mapa_rank(mb, r));
                }
            }
        }
    }
}

// ============================================================================
// Kernel 3: out[t][n] = fb[t]·Wlin[n] + blin[n]   (20 x 100000, K=256)
// HBM-bound on Wlin (102.4 MB). smem-tiled, packed f32x2 FMA: each thread
// owns one column n with 10 packed accumulators (20 timesteps).
// Ws padded to stride 20 (16B aligned, conflict-free LDS.128 weight loads).
// ============================================================================
__global__ void __launch_bounds__(256, 4)
proj_kernel(const float* __restrict__ Wlin, const float* __restrict__ blin,
            float* __restrict__ out)
{
    __shared__ float fbT[256 * 20];   // [k][t], row stride 20 floats (16B-aligned)
    __shared__ float Ws[256 * 20];    // [n_local][16 k + 4 pad], 16B-aligned rows

    const int tid = threadIdx.x;
    const int n0  = blockIdx.x * 256;
    const int n   = n0 + tid;
    const bool valid = (n < NC);

    // fbT: transpose fb[20][256] -> fbT[k][t]; tid == k
    #pragma unroll
    for (int t = 0; t < SEQ; t++) fbT[tid * 20 + t] = g_fb[t * 256 + tid];

    const float bb = valid ? blin[n] : 0.0f;
    unsigned long long acc[10];
    {
        const uint32_t bu = __float_as_uint(bb);
        #pragma unroll
        for (int j = 0; j < 10; j++)
            asm("mov.b64 %0, {%1, %1};" : "=l"(acc[j]) : "r"(bu));
    }
    __syncthreads();

    #pragma unroll 1
    for (int kt = 0; kt < 16; kt++) {
        // Stage Wlin tile: 256 rows x 16 cols, coalesced float4 loads.
        #pragma unroll
        for (int it = 0; it < 4; it++) {
            const int idx = tid + it * 256;           // 0..1023
            const int row = idx >> 2, cs = idx & 3;
            float4 v = make_float4(0.f, 0.f, 0.f, 0.f);
            const int nr = n0 + row;
            if (nr < NC)
                v = *(const float4*)(Wlin + (size_t)nr * 256 + kt * 16 + cs * 4);
            *(float4*)&Ws[row * 20 + cs * 4] = v;
        }
        __syncthreads();

        #pragma unroll
        for (int kk4 = 0; kk4 < 4; kk4++) {
            const float4 wv = *(const float4*)&Ws[tid * 20 + kk4 * 4];
            const float wf[4] = {wv.x, wv.y, wv.z, wv.w};
            #pragma unroll
            for (int j = 0; j < 4; j++) {
                unsigned long long w2;
                asm("mov.b64 %0, {%1, %1};" : "=l"(w2) : "r"(__float_as_uint(wf[j])));
                const ulonglong2* fp =
                    (const ulonglong2*)&fbT[(kt * 16 + kk4 * 4 + j) * 20];
                #pragma unroll
                for (int q = 0; q < 5; q++) {
                    const ulonglong2 fv = fp[q];   // broadcast LDS.128
                    asm("fma.rn.f32x2 %0, %1, %2, %0;" : "+l"(acc[2*q])   : "l"(w2), "l"(fv.x));
                    asm("fma.rn.f32x2 %0, %1, %2, %0;" : "+l"(acc[2*q+1]) : "l"(w2), "l"(fv.y));
                }
            }
        }
        __syncthreads();
    }

    if (valid) {
        #pragma unroll
        for (int j = 0; j < 10; j++) {
            uint32_t lo, hi;
            asm("mov.b64 {%0, %1}, %2;" : "=r"(lo), "=r"(hi) : "l"(acc[j]));
            out[(size_t)(2 * j)     * NC + n] = __uint_as_float(lo);
            out[(size_t)(2 * j + 1) * NC + n] = __uint_as_float(hi);
        }
    }
}

// ============================================================================
// Launch
// ============================================================================
extern "C" void kernel_launch(void* const* d_in, const int* in_sizes, int n_in,
                              void* d_out, int out_size)
{
    (void)in_sizes; (void)n_in; (void)out_size;
    const float* x     = (const float*)d_in[0];
    const float* h0f   = (const float*)d_in[1];
    const float* c0f   = (const float*)d_in[2];
    const float* h0b   = (const float*)d_in[3];
    const float* c0b   = (const float*)d_in[4];
    const float* h0l   = (const float*)d_in[5];
    const float* c0l   = (const float*)d_in[6];
    const float* Wih_f = (const float*)d_in[7];
    const float* Whh_f = (const float*)d_in[8];
    const float* bih_f = (const float*)d_in[9];
    const float* bhh_f = (const float*)d_in[10];
    const float* Wih_b = (const float*)d_in[11];
    const float* Whh_b = (const float*)d_in[12];
    const float* bih_b = (const float*)d_in[13];
    const float* bhh_b = (const float*)d_in[14];
    const float* Wih_l = (const float*)d_in[15];
    const float* Whh_l = (const float*)d_in[16];
    const float* bih_l = (const float*)d_in[17];
    const float* bhh_l = (const float*)d_in[18];
    const float* Wlin  = (const float*)d_in[19];
    const float* blin  = (const float*)d_in[20];
    float* out = (float*)d_out;

    lstm_fb_kernel<<<8, 512>>>(x, h0f, c0f, h0b, c0b,
                               Wih_f, Whh_f, bih_f, bhh_f,
                               Wih_b, Whh_b, bih_b, bhh_b);
    lstm_l_kernel<<<8, 512>>>(h0l, c0l, Wih_l, Whh_l, bih_l, bhh_l);
    proj_kernel<<<(NC + 255) / 256, 256>>>(Wlin, blin, out);
}

// round 16
// speedup vs baseline: 1.3195x; 1.3072x over previous
#include <cuda_runtime.h>
#include <cstdint>
#include <math.h>

#define SEQ 20
#define H   128
#define NC  100000

// Scratch (allocation-free rule: __device__ globals)
__device__ float g_comb[SEQ * 256];   // [t][ fwd(128) | bwd(128) ]
__device__ float g_fb[SEQ * 256];     // [t][256]  output of 2H LSTM

// ---------------------------------------------------------------------------
// Fast transcendentals via MUFU (ex2/rcp approx ~2^-22 accurate).
// ---------------------------------------------------------------------------
__device__ __forceinline__ float ex2f(float x) { float y; asm("ex2.approx.f32 %0, %1;" : "=f"(y) : "f"(x)); return y; }
__device__ __forceinline__ float rcpf(float x) { float y; asm("rcp.approx.f32 %0, %1;" : "=f"(y) : "f"(x)); return y; }
__device__ __forceinline__ float sigm(float x) {
    return rcpf(1.0f + ex2f(-1.4426950408889634f * x));
}
__device__ __forceinline__ float tanh_fast(float x) {
    return fmaf(2.0f, rcpf(1.0f + ex2f(-2.8853900817779268f * x)), -1.0f);
}

// ---------------------------------------------------------------------------
// DSMEM async-proxy signaling: st.async with mbarrier complete_tx.
// NO cluster-scope generic fences in the hot loop (avoids per-step CCTL.IVALL).
// ---------------------------------------------------------------------------
__device__ __forceinline__ uint32_t smem_u32(const void* p) {
    return (uint32_t)__cvta_generic_to_shared(p);
}
__device__ __forceinline__ uint32_t mapa_rank(uint32_t laddr, uint32_t rank) {
    uint32_t r;
    asm("mapa.shared::cluster.u32 %0, %1, %2;" : "=r"(r) : "r"(laddr), "r"(rank));
    return r;
}
// Store 4 bytes into peer-CTA smem; peer's mbarrier gets complete_tx(4).
__device__ __forceinline__ void st_async_f32(uint32_t raddr, float v, uint32_t rmbar) {
    asm volatile("st.async.shared::cluster.mbarrier::complete_tx::bytes.b32 [%0], %1, [%2];"
                 :: "r"(raddr), "r"(__float_as_uint(v)), "r"(rmbar) : "memory");
}
__device__ __forceinline__ void mbar_init(uint32_t laddr, uint32_t cnt) {
    asm volatile("mbarrier.init.shared.b64 [%0], %1;" :: "r"(laddr), "r"(cnt) : "memory");
}
// arrive (count 1) + expect tx bytes for the current phase
__device__ __forceinline__ void mbar_arm(uint32_t laddr, uint32_t txb) {
    asm volatile("mbarrier.arrive.expect_tx.shared.b64 _, [%0], %1;"
                 :: "r"(laddr), "r"(txb) : "memory");
}
// CTA-scope acquire wait (async-proxy writes made visible by complete_tx)
__device__ __forceinline__ void mbar_wait(uint32_t laddr, uint32_t parity) {
    asm volatile(
        "{\n\t"
        ".reg .pred P;\n\t"
        "WL%=:\n\t"
        "mbarrier.try_wait.parity.acquire.cta.shared::cta.b64 P, [%0], %1;\n\t"
        "@P bra WD%=;\n\t"
        "bra WL%=;\n\t"
        "WD%=:\n\t"
        "}"
        :: "r"(laddr), "r"(parity) : "memory");
}
#define CLUSTER_SYNC() do { \
    asm volatile("barrier.cluster.arrive.aligned;" ::: "memory"); \
    asm volatile("barrier.cluster.wait.aligned;"   ::: "memory"); } while (0)

// ============================================================================
// Kernel 1: forward + backward H=128 LSTM scans.
// grid = 4, cluster = 2: blocks {0,1} = forward cell, {2,3} = backward cell.
// Phase A precomputes xg[t][g] = Wih·x[t] + biases for all t (x known
// upfront), so the serial scan only needs Whh: 512x128 per cell split over
// 2 CTAs, 64 fp32 weights per thread in registers (rl=tid>>1 gate row,
// seg=tid&1 half). Per-step h broadcast: st.async to both ranks.
// ============================================================================
__global__ void __launch_bounds__(512, 1) __cluster_dims__(2, 1, 1)
lstm_fb_kernel(const float* __restrict__ x,
               const float* __restrict__ h0f, const float* __restrict__ c0f,
               const float* __restrict__ h0b, const float* __restrict__ c0b,
               const float* __restrict__ Wih_f, const float* __restrict__ Whh_f,
               const float* __restrict__ bih_f, const float* __restrict__ bhh_f,
               const float* __restrict__ Wih_b, const float* __restrict__ Whh_b,
               const float* __restrict__ bih_b, const float* __restrict__ bhh_b)
{
    __shared__ float xs[SEQ * H];        // 10 KB
    __shared__ float xg[SEQ * 256];      // 20 KB  (per-CTA gate slice, incl bias)
    __shared__ float hbuf[2][H];
    __shared__ float gates[256];
    __shared__ __align__(8) uint64_t mbar[2];

    const int tid  = threadIdx.x;
    const int cell = blockIdx.x >> 1;    // 0 = fwd, 1 = bwd
    uint32_t rank;
    asm("mov.u32 %0, %%cluster_ctarank;" : "=r"(rank));

    const float* Wih = cell ? Wih_b : Wih_f;
    const float* Whh = cell ? Whh_b : Whh_f;
    const float* bih = cell ? bih_b : bih_f;
    const float* bhh = cell ? bhh_b : bhh_f;
    const float* h0  = cell ? h0b : h0f;
    const float* c0  = cell ? c0b : c0f;

    const int rl   = tid >> 1;           // 0..255 local gate row
    const int seg  = tid & 1;            // 64-float half
    const int type = rl >> 6;            // i,f,g,o
    const int ul   = rl & 63;
    const int u    = (int)rank * 64 + ul;   // unit within cell (0..127)
    const int g    = type * H + u;          // gate row in [0,512)

    const uint32_t TXB = 2u * 64u * 4u;  // bytes per phase per consumer CTA

    if (tid == 0) {
        mbar_init(smem_u32(&mbar[0]), 1);
        mbar_init(smem_u32(&mbar[1]), 1);
        mbar_arm(smem_u32(&mbar[0]), TXB);   // phase 0 (completes end of step 1)
        mbar_arm(smem_u32(&mbar[1]), TXB);   // phase 0 (completes end of step 0)
    }
    for (int i = tid; i < SEQ * H; i += 512) xs[i] = x[i];
    if (tid < H) hbuf[0][tid] = h0[tid];
    float creg = 0.0f;
    if (tid < 64) creg = c0[(int)rank * 64 + tid];
    const float bias = bih[g] + bhh[g];
    __syncthreads();

    float w[64];
    // ---- Phase A: xg[t] = Wih·x[tx] + bias for all t (Wih streamed via w) ----
    {
        const float* wsrc = Wih + (size_t)g * H + seg * 64;
        #pragma unroll
        for (int q = 0; q < 16; q++) {
            float4 v = *(const float4*)(wsrc + q * 4);
            w[q*4+0] = v.x; w[q*4+1] = v.y; w[q*4+2] = v.z; w[q*4+3] = v.w;
        }
        #pragma unroll 1
        for (int t = 0; t < SEQ; t++) {
            const int tx = cell ? (SEQ - 1 - t) : t;
            const float* vs = xs + tx * H + seg * 64;
            float a0 = 0.f, a1 = 0.f, a2 = 0.f, a3 = 0.f;
            #pragma unroll
            for (int q = 0; q < 16; q++) {
                float4 v = *(const float4*)(vs + q * 4);
                a0 += w[q*4+0] * v.x; a1 += w[q*4+1] * v.y;
                a2 += w[q*4+2] * v.z; a3 += w[q*4+3] * v.w;
            }
            float s = (a0 + a1) + (a2 + a3);
            s += __shfl_xor_sync(0xffffffffu, s, 1);
            if (seg == 0) xg[t * 256 + rl] = s + bias;
        }
    }
    // ---- reload w[] with Whh row half ----
    {
        const float* wsrc = Whh + (size_t)g * H + seg * 64;
        #pragma unroll
        for (int q = 0; q < 16; q++) {
            float4 v = *(const float4*)(wsrc + q * 4);
            w[q*4+0] = v.x; w[q*4+1] = v.y; w[q*4+2] = v.z; w[q*4+3] = v.w;
        }
    }
    __syncthreads();
    CLUSTER_SYNC();   // publish mbarrier init/arm cluster-wide (one-time CCTL ok)

    #pragma unroll 1
    for (int t = 0; t < SEQ; t++) {
        const int cur = t & 1, nxt = cur ^ 1;
        if (t > 0) {
            mbar_wait(smem_u32(&mbar[cur]), ((t - 1) >> 1) & 1);
            if (tid == 0) mbar_arm(smem_u32(&mbar[cur]), TXB);  // next phase
        }

        const float* vs = hbuf[cur] + seg * 64;
        float a0 = 0.f, a1 = 0.f, a2 = 0.f, a3 = 0.f;
        #pragma unroll
        for (int q = 0; q < 16; q++) {
            float4 v = *(const float4*)(vs + q * 4);
            a0 += w[q*4+0] * v.x; a1 += w[q*4+1] * v.y;
            a2 += w[q*4+2] * v.z; a3 += w[q*4+3] * v.w;
        }
        float s = (a0 + a1) + (a2 + a3);
        s += __shfl_xor_sync(0xffffffffu, s, 1);
        if (seg == 0) gates[rl] = s + xg[t * 256 + rl];
        __syncthreads();   // orders tid0's arm before the st.async below, too

        if (tid < 64) {
            const float gi = gates[tid],       gf = gates[64 + tid];
            const float gc = gates[128 + tid], go = gates[192 + tid];
            creg = sigm(gf) * creg + sigm(gi) * tanh_fast(gc);
            const float h2 = sigm(go) * tanh_fast(creg);
            g_comb[t * 256 + cell * 128 + (int)rank * 64 + tid] = h2;
            if (t < SEQ - 1) {
                const uint32_t laddr = smem_u32(&hbuf[nxt][(int)rank * 64 + tid]);
                const uint32_t lmbar = smem_u32(&mbar[nxt]);
                st_async_f32(mapa_rank(laddr, 0), h2, mapa_rank(lmbar, 0));
                st_async_f32(mapa_rank(laddr, 1), h2, mapa_rank(lmbar, 1));
            }
        }
    }
}

// ============================================================================
// Kernel 2: 2H=256 LSTM over comb. 8-CTA cluster; each CTA owns 32 of 256
// units (128 gate rows of 8H=1024). Phase A precomputes xg[t][g] =
// Wih_l[g]·comb[t] + biases for all t. Serial scan needs only Whh_l
// (register-resident) + st.async h broadcast (no cluster fences in loop).
// ============================================================================
__global__ void __launch_bounds__(512, 1) __cluster_dims__(8, 1, 1)
lstm_l_kernel(const float* __restrict__ h0l, const float* __restrict__ c0l,
              const float* __restrict__ Wih_l, const float* __restrict__ Whh_l,
              const float* __restrict__ bih_l, const float* __restrict__ bhh_l)
{
    __shared__ float combs[SEQ * 256];   // 20 KB
    __shared__ float xg[SEQ * 128];      // 10 KB  (per-CTA gate slice)
    __shared__ float hbuf[2][256];
    __shared__ float gates[128];
    __shared__ __align__(8) uint64_t mbar[2];

    const int tid  = threadIdx.x;
    uint32_t rank;
    asm("mov.u32 %0, %%cluster_ctarank;" : "=r"(rank));
    const int gl   = tid >> 2;
    const int seg  = tid & 3;
    const int type = gl >> 5;
    const int ul   = gl & 31;
    const int u    = (int)rank * 32 + ul;  // unit in [0,256)
    const int g    = type * 256 + u;       // gate row in [0,1024)

    const uint32_t TXB = 8u * 32u * 4u;    // bytes per phase per consumer CTA

    if (tid == 0) {
        mbar_init(smem_u32(&mbar[0]), 1);
        mbar_init(smem_u32(&mbar[1]), 1);
        mbar_arm(smem_u32(&mbar[0]), TXB);
        mbar_arm(smem_u32(&mbar[1]), TXB);
    }
    for (int i = tid; i < SEQ * 256; i += 512) combs[i] = g_comb[i];
    if (tid < 256) hbuf[0][tid] = h0l[tid];
    float creg = 0.0f;
    if (tid < 32) creg = c0l[(int)rank * 32 + tid];
    const float bias = bih_l[g] + bhh_l[g];
    __syncthreads();

    float w[64];
    // ---- Phase A: xg for all timesteps (Wih_l temporarily in w[]) ----
    {
        const float* wsrc = Wih_l + (size_t)g * 256 + seg * 64;
        #pragma unroll
        for (int q = 0; q < 16; q++) {
            float4 v = *(const float4*)(wsrc + q * 4);
            w[q*4+0] = v.x; w[q*4+1] = v.y; w[q*4+2] = v.z; w[q*4+3] = v.w;
        }
        #pragma unroll 1
        for (int t = 0; t < SEQ; t++) {
            const float* vs = combs + t * 256 + seg * 64;
            float a0 = 0.f, a1 = 0.f, a2 = 0.f, a3 = 0.f;
            #pragma unroll
            for (int q = 0; q < 16; q++) {
                float4 v = *(const float4*)(vs + q * 4);
                a0 += w[q*4+0] * v.x; a1 += w[q*4+1] * v.y;
                a2 += w[q*4+2] * v.z; a3 += w[q*4+3] * v.w;
            }
            float s = (a0 + a1) + (a2 + a3);
            s += __shfl_xor_sync(0xffffffffu, s, 1);
            s += __shfl_xor_sync(0xffffffffu, s, 2);
            if (seg == 0) xg[t * 128 + gl] = s + bias;
        }
    }
    // ---- reload w[] with Whh_l row segment ----
    {
        const float* wsrc = Whh_l + (size_t)g * 256 + seg * 64;
        #pragma unroll
        for (int q = 0; q < 16; q++) {
            float4 v = *(const float4*)(wsrc + q * 4);
            w[q*4+0] = v.x; w[q*4+1] = v.y; w[q*4+2] = v.z; w[q*4+3] = v.w;
        }
    }
    __syncthreads();
    CLUSTER_SYNC();   // publish mbarrier init/arm cluster-wide (one-time)

    #pragma unroll 1
    for (int t = 0; t < SEQ; t++) {
        const int cur = t & 1, nxt = cur ^ 1;
        if (t > 0) {
            mbar_wait(smem_u32(&mbar[cur]), ((t - 1) >> 1) & 1);
            if (tid == 0) mbar_arm(smem_u32(&mbar[cur]), TXB);
        }

        const float* vs = hbuf[cur] + seg * 64;
        float a0 = 0.f, a1 = 0.f, a2 = 0.f, a3 = 0.f;
        #pragma unroll
        for (int q = 0; q < 16; q++) {
            float4 v = *(const float4*)(vs + q * 4);
            a0 += w[q*4+0] * v.x; a1 += w[q*4+1] * v.y;
            a2 += w[q*4+2] * v.z; a3 += w[q*4+3] * v.w;
        }
        float s = (a0 + a1) + (a2 + a3);
        s += __shfl_xor_sync(0xffffffffu, s, 1);
        s += __shfl_xor_sync(0xffffffffu, s, 2);
        if (seg == 0) gates[gl] = s + xg[t * 128 + gl];
        __syncthreads();

        if (tid < 32) {
            const float gi = gates[tid],      gf = gates[32 + tid];
            const float gc = gates[64 + tid], go = gates[96 + tid];
            creg = sigm(gf) * creg + sigm(gi) * tanh_fast(gc);
            const float h2 = sigm(go) * tanh_fast(creg);
            g_fb[t * 256 + (int)rank * 32 + tid] = h2;
            if (t < SEQ - 1) {
                const uint32_t laddr = smem_u32(&hbuf[nxt][(int)rank * 32 + tid]);
                const uint32_t lmbar = smem_u32(&mbar[nxt]);
                #pragma unroll
                for (int r = 0; r < 8; r++)
                    st_async_f32(mapa_rank(laddr, r), h2, mapa_rank(lmbar, r));
            }
        }
    }
}

// ============================================================================
// Kernel 3: out[t][n] = fb[t]·Wlin[n] + blin[n]   (20 x 100000, K=256)
// smem-tiled, packed f32x2 FMA; one column per thread, 10 packed accs.
// ============================================================================
__global__ void __launch_bounds__(256, 4)
proj_kernel(const float* __restrict__ Wlin, const float* __restrict__ blin,
            float* __restrict__ out)
{
    __shared__ float fbT[256 * 20];   // [k][t], row stride 20 floats (16B-aligned)
    __shared__ float Ws[256 * 20];    // [n_local][16 k + 4 pad]

    const int tid = threadIdx.x;
    const int n0  = blockIdx.x * 256;
    const int n   = n0 + tid;
    const bool valid = (n < NC);

    #pragma unroll
    for (int t = 0; t < SEQ; t++) fbT[tid * 20 + t] = g_fb[t * 256 + tid];

    const float bb = valid ? blin[n] : 0.0f;
    unsigned long long acc[10];
    {
        const uint32_t bu = __float_as_uint(bb);
        #pragma unroll
        for (int j = 0; j < 10; j++)
            asm("mov.b64 %0, {%1, %1};" : "=l"(acc[j]) : "r"(bu));
    }
    __syncthreads();

    #pragma unroll 1
    for (int kt = 0; kt < 16; kt++) {
        #pragma unroll
        for (int it = 0; it < 4; it++) {
            const int idx = tid + it * 256;
            const int row = idx >> 2, cs = idx & 3;
            float4 v = make_float4(0.f, 0.f, 0.f, 0.f);
            const int nr = n0 + row;
            if (nr < NC)
                v = *(const float4*)(Wlin + (size_t)nr * 256 + kt * 16 + cs * 4);
            *(float4*)&Ws[row * 20 + cs * 4] = v;
        }
        __syncthreads();

        #pragma unroll
        for (int kk4 = 0; kk4 < 4; kk4++) {
            const float4 wv = *(const float4*)&Ws[tid * 20 + kk4 * 4];
            const float wf[4] = {wv.x, wv.y, wv.z, wv.w};
            #pragma unroll
            for (int j = 0; j < 4; j++) {
                unsigned long long w2;
                asm("mov.b64 %0, {%1, %1};" : "=l"(w2) : "r"(__float_as_uint(wf[j])));
                const ulonglong2* fp =
                    (const ulonglong2*)&fbT[(kt * 16 + kk4 * 4 + j) * 20];
                #pragma unroll
                for (int q = 0; q < 5; q++) {
                    const ulonglong2 fv = fp[q];
                    asm("fma.rn.f32x2 %0, %1, %2, %0;" : "+l"(acc[2*q])   : "l"(w2), "l"(fv.x));
                    asm("fma.rn.f32x2 %0, %1, %2, %0;" : "+l"(acc[2*q+1]) : "l"(w2), "l"(fv.y));
                }
            }
        }
        __syncthreads();
    }

    if (valid) {
        #pragma unroll
        for (int j = 0; j < 10; j++) {
            uint32_t lo, hi;
            asm("mov.b64 {%0, %1}, %2;" : "=r"(lo), "=r"(hi) : "l"(acc[j]));
            out[(size_t)(2 * j)     * NC + n] = __uint_as_float(lo);
            out[(size_t)(2 * j + 1) * NC + n] = __uint_as_float(hi);
        }
    }
}

// ============================================================================
// Launch
// ============================================================================
extern "C" void kernel_launch(void* const* d_in, const int* in_sizes, int n_in,
                              void* d_out, int out_size)
{
    (void)in_sizes; (void)n_in; (void)out_size;
    const float* x     = (const float*)d_in[0];
    const float* h0f   = (const float*)d_in[1];
    const float* c0f   = (const float*)d_in[2];
    const float* h0b   = (const float*)d_in[3];
    const float* c0b   = (const float*)d_in[4];
    const float* h0l   = (const float*)d_in[5];
    const float* c0l   = (const float*)d_in[6];
    const float* Wih_f = (const float*)d_in[7];
    const float* Whh_f = (const float*)d_in[8];
    const float* bih_f = (const float*)d_in[9];
    const float* bhh_f = (const float*)d_in[10];
    const float* Wih_b = (const float*)d_in[11];
    const float* Whh_b = (const float*)d_in[12];
    const float* bih_b = (const float*)d_in[13];
    const float* bhh_b = (const float*)d_in[14];
    const float* Wih_l = (const float*)d_in[15];
    const float* Whh_l = (const float*)d_in[16];
    const float* bih_l = (const float*)d_in[17];
    const float* bhh_l = (const float*)d_in[18];
    const float* Wlin  = (const float*)d_in[19];
    const float* blin  = (const float*)d_in[20];
    float* out = (float*)d_out;

    lstm_fb_kernel<<<4, 512>>>(x, h0f, c0f, h0b, c0b,
                               Wih_f, Whh_f, bih_f, bhh_f,
                               Wih_b, Whh_b, bih_b, bhh_b);
    lstm_l_kernel<<<8, 512>>>(h0l, c0l, Wih_l, Whh_l, bih_l, bhh_l);
    proj_kernel<<<(NC + 255) / 256, 256>>>(Wlin, blin, out);
}